// round 12
// baseline (speedup 1.0000x reference)
#include <cuda_runtime.h>
#include <cuda_fp16.h>
#include <cstdint>

#define M_TOK 65536   // B*N
#define C_DIM 1024
#define H_DIM 512
#define Q_DIM 256

// ----------------- device-global scratch ----------------------------------
__device__ float g_mu[M_TOK];
__device__ float g_rstd[M_TOK];
__device__ float g_bias2[H_DIM];
// intermediates stored as fp16 hi/lo pairs, [m][k] layout
__device__ __half g_h1h[(size_t)M_TOK * H_DIM];
__device__ __half g_h1l[(size_t)M_TOK * H_DIM];
__device__ __half g_h2h[(size_t)M_TOK * H_DIM];
__device__ __half g_h2l[(size_t)M_TOK * H_DIM];
__device__ float  g_h3[(size_t)M_TOK * Q_DIM];
// fp16 weights (single rounding), TRANSPOSED [n][k] layout (k contiguous)
__device__ __half g_W1[H_DIM * C_DIM];
__device__ __half g_W2[H_DIM * H_DIM];
__device__ __half g_W3[Q_DIM * H_DIM];
__device__ int   g_fix_count;
__device__ int   g_fix_list[M_TOK];

// ----------------- helpers ------------------------------------------------
__device__ __forceinline__ float gelu_f(float v) {
    return 0.5f * v * (1.0f + erff(v * 0.70710678118654752440f));
}
__device__ __forceinline__ void h16split(float x, __half& h, __half& l) {
    h = __float2half_rn(x);
    l = __float2half_rn(x - __half2float(h));
}
__device__ __forceinline__ uint32_t pack2(__half a, __half b) {
    __half2 h2 = __halves2half2(a, b);
    return *reinterpret_cast<uint32_t*>(&h2);
}
#define CPA16(dst, src) \
    asm volatile("cp.async.cg.shared.global [%0], [%1], 16;" :: "r"(dst), "l"(src) : "memory")
#define CPA_COMMIT() asm volatile("cp.async.commit_group;" ::: "memory")
#define CPA_WAIT0()  asm volatile("cp.async.wait_group 0;" ::: "memory")
__device__ __forceinline__ uint32_t smem_u32(const void* p) {
    uint32_t a;
    asm("{ .reg .u64 t; cvta.to.shared.u64 t, %1; cvt.u32.u64 %0, t; }" : "=r"(a) : "l"(p));
    return a;
}
__device__ __forceinline__ void ldsm4(uint32_t* r, uint32_t addr) {
    asm volatile("ldmatrix.sync.aligned.m8n8.x4.shared.b16 {%0,%1,%2,%3}, [%4];"
                 : "=r"(r[0]), "=r"(r[1]), "=r"(r[2]), "=r"(r[3]) : "r"(addr));
}
__device__ __forceinline__ void mma16(float* d, const uint32_t* a, uint32_t b0, uint32_t b1) {
    asm volatile(
        "mma.sync.aligned.m16n8k16.row.col.f32.f16.f16.f32 "
        "{%0,%1,%2,%3}, {%4,%5,%6,%7}, {%8,%9}, {%0,%1,%2,%3};"
        : "+f"(d[0]), "+f"(d[1]), "+f"(d[2]), "+f"(d[3])
        : "r"(a[0]), "r"(a[1]), "r"(a[2]), "r"(a[3]), "r"(b0), "r"(b1));
}

// ----------------- LN stats ------------------------------------------------
__global__ __launch_bounds__(256)
void ln_stats_kernel(const float* __restrict__ x) {
    int row = (blockIdx.x * 256 + threadIdx.x) >> 5;
    int lane = threadIdx.x & 31;
    const float4* xr = (const float4*)(x + (size_t)row * C_DIM);
    float s = 0.f, ss = 0.f;
#pragma unroll
    for (int i = 0; i < C_DIM / 128; ++i) {
        float4 v = xr[lane + 32 * i];
        s  += v.x + v.y + v.z + v.w;
        ss += v.x * v.x + v.y * v.y + v.z * v.z + v.w * v.w;
    }
#pragma unroll
    for (int o = 16; o; o >>= 1) {
        s  += __shfl_xor_sync(0xffffffffu, s, o);
        ss += __shfl_xor_sync(0xffffffffu, ss, o);
    }
    if (lane == 0) {
        float mu = s * (1.0f / C_DIM);
        float var = ss * (1.0f / C_DIM) - mu * mu;
        g_mu[row] = mu;
        g_rstd[row] = rsqrtf(var + 1e-5f);
    }
}

// ----------------- weight prep: transpose + fp16 round ----------------------
__global__ void prep_w_kernel(const float* __restrict__ WL,
                              const float* __restrict__ Wl1,
                              const float* __restrict__ Wl2) {
    int i = blockIdx.x * blockDim.x + threadIdx.x;
    if (i == 0) g_fix_count = 0;
    const int S1 = H_DIM * C_DIM;
    const int S2 = S1 + H_DIM * H_DIM;
    const int S3 = S2 + Q_DIM * H_DIM;
    if (i < S1) {
        int n = i / C_DIM, k = i % C_DIM;
        g_W1[i] = __float2half_rn(WL[(size_t)k * H_DIM + n]);
    } else if (i < S2) {
        int j = i - S1;
        int n = j / H_DIM, k = j % H_DIM;          // Wl1 top half: rows 0..511
        g_W2[j] = __float2half_rn(Wl1[(size_t)k * H_DIM + n]);
    } else if (i < S3) {
        int j = i - S2;
        int n = j / H_DIM, k = j % H_DIM;
        g_W3[j] = __float2half_rn(Wl2[(size_t)k * Q_DIM + n]);
    }
}

// ----------------- bias2 = noise_feature @ W_l1[512:,:] (exact fp32) -------
__global__ void bias2_kernel(const float* __restrict__ nf,
                             const float* __restrict__ Wl1) {
    int j = blockIdx.x * blockDim.x + threadIdx.x;
    const float* wp = Wl1 + (size_t)H_DIM * H_DIM + j;
    float s = 0.f;
    for (int k = 0; k < H_DIM; ++k)
        s += nf[k] * wp[(size_t)k * H_DIM];
    g_bias2[j] = s;
}

// ----------------- split-A fp16 mma.sync GEMM (B plain fp16) ---------------
// smem bytes: [0,1024): mu(128f)+rstd(128f)
//   A: base 1024, per buf 20480 (Ah 128 rows x 80B, Al same), 2 bufs -> 41984
//   B: base 41984, per buf 10240 (Bh 128 rows x 80B), 2 bufs -> 62464
#define AB0 1024
#define BB0 41984
#define GEMM_SMEM 62464

template <int MODE>
__global__ __launch_bounds__(256, 2)
void gemm_mma(const float* __restrict__ Aext,
              const float* __restrict__ lns, const float* __restrict__ lnb) {
    constexpr int K  = (MODE == 0) ? C_DIM : H_DIM;
    constexpr int Nn = (MODE == 2) ? Q_DIM : H_DIM;
    constexpr int KB = K / 32;

    extern __shared__ char sm[];
    float* smf = (float*)sm;
    const uint32_t sb = smem_u32(sm);
    const int tid = threadIdx.x;
    const int wid = tid >> 5, lane = tid & 31;
    const int g = lane >> 2, tg = lane & 3;
    const int wm = wid & 3, wn = wid >> 2;
    const int m0 = blockIdx.y * 128, n0 = blockIdx.x * 128;

    const __half* AhG = (MODE == 1) ? g_h1h : g_h2h;   // modes 1,2 only
    const __half* AlG = (MODE == 1) ? g_h1l : g_h2l;
    const __half* BG  = (MODE == 0) ? g_W1 : (MODE == 1 ? g_W2 : g_W3);

    if (MODE == 0 && tid < 128) {
        smf[tid]       = g_mu[m0 + tid];
        smf[128 + tid] = g_rstd[m0 + tid];
    }

    // MODE 0 A staging (fp32 + LN + split): thread -> (row, 16-wide k half)
    const int arow = tid >> 1;
    const int ak   = (tid & 1) * 16;
    const float* aP = (MODE == 0) ? Aext + (size_t)(m0 + arow) * K + ak : nullptr;
    // MODE 1/2 A staging (cp.async): thread -> row arow, 2 chunks of 16B
    const int aq = (tid & 1) * 2;
    const __half* ahP = (MODE != 0) ? AhG + (size_t)(m0 + arow) * K + aq * 8 : nullptr;
    const __half* alP = (MODE != 0) ? AlG + (size_t)(m0 + arow) * K + aq * 8 : nullptr;
    // B staging: thread -> rows brow, brow+64; 16B chunk bq of 4
    const int brow = tid >> 2;
    const int bq   = tid & 3;
    const __half* bP = BG + (size_t)(n0 + brow) * K + bq * 8;

    float4 aR[4];

    auto issueB = [&](int kb, int b) {
        uint32_t base = sb + BB0 + b * 10240 + brow * 80 + bq * 16;
        const __half* sh = bP + kb * 32;
        CPA16(base,           sh);
        CPA16(base + 64 * 80, sh + (size_t)64 * K);
    };
    auto issueA = [&](int kb, int b) {   // modes 1,2
        uint32_t base = sb + AB0 + b * 20480 + arow * 80 + aq * 16;
        const __half* sh = ahP + kb * 32;
        const __half* sl = alP + kb * 32;
        CPA16(base,              sh);
        CPA16(base + 16,         sh + 8);
        CPA16(base + 10240,      sl);
        CPA16(base + 10240 + 16, sl + 8);
    };
    auto loadA = [&](int kb) {           // mode 0
        const float* p = aP + kb * 32;
#pragma unroll
        for (int c = 0; c < 4; ++c) aR[c] = *(const float4*)(p + c * 4);
    };
    auto storeA = [&](int kb, int b) {   // mode 0
        char* dh = sm + AB0 + b * 20480 + arow * 80 + ak * 2;
        char* dl = dh + 10240;
        float mu = smf[arow], rs = smf[128 + arow];
        uint32_t hw[8], lw[8];
#pragma unroll
        for (int c = 0; c < 4; ++c) {
            float4 v = aR[c];
            int k = kb * 32 + ak + c * 4;
            float4 s4 = *(const float4*)(lns + k);
            float4 b4 = *(const float4*)(lnb + k);
            v.x = (v.x - mu) * rs * s4.x + b4.x;
            v.y = (v.y - mu) * rs * s4.y + b4.y;
            v.z = (v.z - mu) * rs * s4.z + b4.z;
            v.w = (v.w - mu) * rs * s4.w + b4.w;
            __half hx, lx, hy, ly, hz, lz, hwv, lwv;
            h16split(v.x, hx, lx); h16split(v.y, hy, ly);
            h16split(v.z, hz, lz); h16split(v.w, hwv, lwv);
            hw[c * 2]     = pack2(hx, hy);
            hw[c * 2 + 1] = pack2(hz, hwv);
            lw[c * 2]     = pack2(lx, ly);
            lw[c * 2 + 1] = pack2(lz, lwv);
        }
        *(uint4*)(dh)      = make_uint4(hw[0], hw[1], hw[2], hw[3]);
        *(uint4*)(dh + 16) = make_uint4(hw[4], hw[5], hw[6], hw[7]);
        *(uint4*)(dl)      = make_uint4(lw[0], lw[1], lw[2], lw[3]);
        *(uint4*)(dl + 16) = make_uint4(lw[4], lw[5], lw[6], lw[7]);
    };

    float acc[2][8][4];
#pragma unroll
    for (int mt = 0; mt < 2; ++mt)
#pragma unroll
        for (int nt = 0; nt < 8; ++nt)
#pragma unroll
            for (int j = 0; j < 4; ++j) acc[mt][nt][j] = 0.f;

    // ldmatrix lane-address components
    const int aRowL = lane & 15;
    const int aKhL  = lane >> 4;
    const int bRowL = (lane & 7) + ((lane >> 4) << 3);
    const int bKbL  = (lane >> 3) & 1;

    auto compute = [&](int b) {
        const uint32_t baseAh = sb + AB0 + b * 20480;
        const uint32_t baseAl = baseAh + 10240;
        const uint32_t baseB  = sb + BB0 + b * 10240;
#pragma unroll
        for (int ck = 0; ck < 2; ++ck) {
            const int k0 = ck * 16;
            const uint32_t aoff = (uint32_t)(aRowL * 80 + (k0 + aKhL * 8) * 2);
            const uint32_t boff = (uint32_t)(bRowL * 80 + (k0 + bKbL * 8) * 2);
            uint32_t ah[2][4], al[2][4];
#pragma unroll
            for (int mt = 0; mt < 2; ++mt) {
                uint32_t ro = (uint32_t)((wm * 32 + mt * 16) * 80);
                ldsm4(ah[mt], baseAh + ro + aoff);
                ldsm4(al[mt], baseAl + ro + aoff);
            }
#pragma unroll
            for (int p = 0; p < 4; ++p) {
                uint32_t co = (uint32_t)((wn * 64 + p * 16) * 80);
                uint32_t bh4[4];
                ldsm4(bh4, baseB + co + boff);
                const int n0t = p * 2, n1t = p * 2 + 1;
                // hi·B (4 independent accumulators)
                mma16(acc[0][n0t], ah[0], bh4[0], bh4[1]);
                mma16(acc[1][n0t], ah[1], bh4[0], bh4[1]);
                mma16(acc[0][n1t], ah[0], bh4[2], bh4[3]);
                mma16(acc[1][n1t], ah[1], bh4[2], bh4[3]);
                // lo·B
                mma16(acc[0][n0t], al[0], bh4[0], bh4[1]);
                mma16(acc[1][n0t], al[1], bh4[0], bh4[1]);
                mma16(acc[0][n1t], al[0], bh4[2], bh4[3]);
                mma16(acc[1][n1t], al[1], bh4[2], bh4[3]);
            }
        }
    };

    // ---- pipeline ----
    int buf = 0;
    if (MODE == 0) {
        issueB(0, 0);
        CPA_COMMIT();
        loadA(0);
        __syncthreads();          // mu/rstd visible
        storeA(0, 0);
        CPA_WAIT0();
        __syncthreads();
        for (int kt = 0; kt < KB; ++kt) {
            if (kt + 1 < KB) {
                issueB(kt + 1, buf ^ 1);
                CPA_COMMIT();
                loadA(kt + 1);
            }
            compute(buf);
            if (kt + 1 < KB) storeA(kt + 1, buf ^ 1);
            CPA_WAIT0();
            __syncthreads();
            buf ^= 1;
        }
    } else {
        issueB(0, 0);
        issueA(0, 0);
        CPA_COMMIT();
        CPA_WAIT0();
        __syncthreads();
        for (int kt = 0; kt < KB; ++kt) {
            if (kt + 1 < KB) {
                issueB(kt + 1, buf ^ 1);
                issueA(kt + 1, buf ^ 1);
                CPA_COMMIT();
            }
            compute(buf);
            CPA_WAIT0();
            __syncthreads();
            buf ^= 1;
        }
    }

    // ---- epilogue ----
#pragma unroll
    for (int mt = 0; mt < 2; ++mt) {
        int r = m0 + wm * 32 + mt * 16 + g;
#pragma unroll
        for (int nt = 0; nt < 8; ++nt) {
            int c = n0 + wn * 64 + nt * 8 + tg * 2;
            float* a4 = acc[mt][nt];
            if (MODE == 2) {
                float2 v0 = make_float2(gelu_f(a4[0]), gelu_f(a4[1]));
                float2 v1 = make_float2(gelu_f(a4[2]), gelu_f(a4[3]));
                *(float2*)(g_h3 + (size_t)r * Nn + c)       = v0;
                *(float2*)(g_h3 + (size_t)(r + 8) * Nn + c) = v1;
            } else {
                float b0 = 0.f, b1 = 0.f;
                if (MODE == 1) { b0 = g_bias2[c]; b1 = g_bias2[c + 1]; }
                float f0 = gelu_f(a4[0] + b0), f1 = gelu_f(a4[1] + b1);
                float f2 = gelu_f(a4[2] + b0), f3 = gelu_f(a4[3] + b1);
                __half h0, l0, h1, l1, h2, l2, h3, l3;
                h16split(f0, h0, l0); h16split(f1, h1, l1);
                h16split(f2, h2, l2); h16split(f3, h3, l3);
                __half* Dh = (MODE == 0) ? g_h1h : g_h2h;
                __half* Dl = (MODE == 0) ? g_h1l : g_h2l;
                *(uint32_t*)(Dh + (size_t)r * Nn + c)       = pack2(h0, h1);
                *(uint32_t*)(Dl + (size_t)r * Nn + c)       = pack2(l0, l1);
                *(uint32_t*)(Dh + (size_t)(r + 8) * Nn + c) = pack2(h2, h3);
                *(uint32_t*)(Dl + (size_t)(r + 8) * Nn + c) = pack2(l2, l3);
            }
        }
    }
}

// ----------------- final: logit, flag-or-write -----------------------------
__global__ __launch_bounds__(256)
void final_kernel(const float* __restrict__ x, const float* __restrict__ prevm,
                  const float* __restrict__ w3, float* __restrict__ out,
                  int write_extra) {
    int row = (blockIdx.x * 256 + threadIdx.x) >> 5;
    int lane = threadIdx.x & 31;
    const float* h3 = g_h3 + (size_t)row * Q_DIM;
    float s = 0.f;
#pragma unroll
    for (int i = 0; i < 8; ++i) s += h3[lane + 32 * i] * w3[lane + 32 * i];
#pragma unroll
    for (int o = 16; o; o >>= 1) s += __shfl_xor_sync(0xffffffffu, s, o);

    float prob = 1.0f / (1.0f + expf(-s));
    float xm = prob * prevm[row];

    if (fabsf(xm - 0.5f) < 3e-3f) {
        if (lane == 0) {
            int idx = atomicAdd(&g_fix_count, 1);
            if (idx < M_TOK) g_fix_list[idx] = row;
        }
        return;
    }
    float m = (xm > 0.5f) ? 1.0f : 0.0f;
    if (lane == 0 && write_extra) {
        out[(size_t)M_TOK * C_DIM + row] = m;
        out[(size_t)M_TOK * C_DIM + M_TOK + row] = (m > 0.f) ? 1.0f : 1e-10f;
    }
    const float4* xr = (const float4*)(x + (size_t)row * C_DIM);
    float4* orow = (float4*)(out + (size_t)row * C_DIM);
#pragma unroll
    for (int i = 0; i < 8; ++i) {
        float4 v = xr[lane + 32 * i];
        v.x *= m; v.y *= m; v.z *= m; v.w *= m;
        orow[lane + 32 * i] = v;
    }
}

// ----------------- fixup: exact fp32 recompute for flagged rows ------------
__global__ __launch_bounds__(256)
void fixup_kernel(const float* __restrict__ x, const float* __restrict__ prevm,
                  const float* __restrict__ WL, const float* __restrict__ Wl1,
                  const float* __restrict__ Wl2, const float* __restrict__ w3,
                  const float* __restrict__ lns, const float* __restrict__ lnb,
                  float* __restrict__ out, int write_extra) {
    __shared__ float a[C_DIM];
    __shared__ float h1s[H_DIM];
    __shared__ float h2s[H_DIM];
    __shared__ float h3s[Q_DIM];
    __shared__ float red[256];
    int cnt = g_fix_count;
    if (cnt > M_TOK) cnt = M_TOK;
    int t = threadIdx.x;

    for (int i = blockIdx.x; i < cnt; i += gridDim.x) {
        int row = g_fix_list[i];
        float mu = g_mu[row], rs = g_rstd[row];
        for (int j = t; j < C_DIM; j += 256)
            a[j] = (x[(size_t)row * C_DIM + j] - mu) * rs * lns[j] + lnb[j];
        __syncthreads();
        for (int j = t; j < H_DIM; j += 256) {
            float acc = 0.f;
            for (int k = 0; k < C_DIM; ++k)
                acc = fmaf(a[k], WL[(size_t)k * H_DIM + j], acc);
            h1s[j] = gelu_f(acc);
        }
        __syncthreads();
        for (int j = t; j < H_DIM; j += 256) {
            float acc = g_bias2[j];
            for (int k = 0; k < H_DIM; ++k)
                acc = fmaf(h1s[k], Wl1[(size_t)k * H_DIM + j], acc);
            h2s[j] = gelu_f(acc);
        }
        __syncthreads();
        for (int j = t; j < Q_DIM; j += 256) {
            float acc = 0.f;
            for (int k = 0; k < H_DIM; ++k)
                acc = fmaf(h2s[k], Wl2[(size_t)k * Q_DIM + j], acc);
            h3s[j] = gelu_f(acc);
        }
        __syncthreads();
        red[t] = (t < Q_DIM) ? h3s[t] * w3[t] : 0.f;
        __syncthreads();
        for (int o = 128; o; o >>= 1) {
            if (t < o) red[t] += red[t + o];
            __syncthreads();
        }
        float s = red[0];
        float prob = 1.0f / (1.0f + expf(-s));
        float m = (prob * prevm[row] > 0.5f) ? 1.0f : 0.0f;
        if (t == 0 && write_extra) {
            out[(size_t)M_TOK * C_DIM + row] = m;
            out[(size_t)M_TOK * C_DIM + M_TOK + row] = (m > 0.f) ? 1.0f : 1e-10f;
        }
        for (int j = t; j < C_DIM; j += 256)
            out[(size_t)row * C_DIM + j] = x[(size_t)row * C_DIM + j] * m;
        __syncthreads();
    }
}

// ----------------- launch ---------------------------------------------------
extern "C" void kernel_launch(void* const* d_in, const int* in_sizes, int n_in,
                              void* d_out, int out_size) {
    const float* x   = (const float*)d_in[0];
    const float* nf  = (const float*)d_in[1];
    const float* pm  = (const float*)d_in[2];
    const float* lns = (const float*)d_in[3];
    const float* lnb = (const float*)d_in[4];
    const float* WL  = (const float*)d_in[5];
    const float* Wl1 = (const float*)d_in[6];
    const float* Wl2 = (const float*)d_in[7];
    const float* W3  = (const float*)d_in[8];
    float* out = (float*)d_out;

    cudaFuncSetAttribute(gemm_mma<0>, cudaFuncAttributeMaxDynamicSharedMemorySize, GEMM_SMEM);
    cudaFuncSetAttribute(gemm_mma<1>, cudaFuncAttributeMaxDynamicSharedMemorySize, GEMM_SMEM);
    cudaFuncSetAttribute(gemm_mma<2>, cudaFuncAttributeMaxDynamicSharedMemorySize, GEMM_SMEM);

    ln_stats_kernel<<<M_TOK / 8, 256>>>(x);
    prep_w_kernel<<<(H_DIM * C_DIM + H_DIM * H_DIM + Q_DIM * H_DIM + 255) / 256, 256>>>(WL, Wl1, Wl2);
    bias2_kernel<<<2, 256>>>(nf, Wl1);

    gemm_mma<0><<<dim3(H_DIM / 128, M_TOK / 128), 256, GEMM_SMEM>>>(x, lns, lnb);
    gemm_mma<1><<<dim3(H_DIM / 128, M_TOK / 128), 256, GEMM_SMEM>>>(nullptr, nullptr, nullptr);
    gemm_mma<2><<<dim3(Q_DIM / 128, M_TOK / 128), 256, GEMM_SMEM>>>(nullptr, nullptr, nullptr);

    int extra = (out_size >= M_TOK * C_DIM + 2 * M_TOK) ? 1 : 0;
    final_kernel<<<M_TOK / 8, 256>>>(x, pm, W3, out, extra);
    fixup_kernel<<<512, 256>>>(x, pm, WL, Wl1, Wl2, W3, lns, lnb, out, extra);
}

// round 13
// speedup vs baseline: 6.2620x; 6.2620x over previous
#include <cuda_runtime.h>
#include <cuda_fp16.h>
#include <cstdint>

#define M_TOK 65536   // B*N
#define C_DIM 1024
#define H_DIM 512
#define Q_DIM 256

// ----------------- device-global scratch ----------------------------------
__device__ float g_mu[M_TOK];
__device__ float g_rstd[M_TOK];
__device__ float g_bias2[H_DIM];
// intermediates stored as fp16 hi/lo pairs, [m][k] layout
__device__ __half g_h1h[(size_t)M_TOK * H_DIM];
__device__ __half g_h1l[(size_t)M_TOK * H_DIM];
__device__ __half g_h2h[(size_t)M_TOK * H_DIM];
__device__ __half g_h2l[(size_t)M_TOK * H_DIM];
__device__ float  g_h3[(size_t)M_TOK * Q_DIM];
// fp16 weights (single rounding), TRANSPOSED [n][k] layout (k contiguous)
__device__ __half g_W1[H_DIM * C_DIM];
__device__ __half g_W2[H_DIM * H_DIM];
__device__ __half g_W3[Q_DIM * H_DIM];
__device__ int   g_fix_count;
__device__ int   g_fix_list[M_TOK];

// ----------------- helpers ------------------------------------------------
__device__ __forceinline__ float gelu_f(float v) {
    return 0.5f * v * (1.0f + erff(v * 0.70710678118654752440f));
}
__device__ __forceinline__ void h16split(float x, __half& h, __half& l) {
    h = __float2half_rn(x);
    l = __float2half_rn(x - __half2float(h));
}
__device__ __forceinline__ uint32_t pack2(__half a, __half b) {
    __half2 h2 = __halves2half2(a, b);
    return *reinterpret_cast<uint32_t*>(&h2);
}
#define CPA16(dst, src) \
    asm volatile("cp.async.cg.shared.global [%0], [%1], 16;" :: "r"(dst), "l"(src) : "memory")
#define CPA_COMMIT() asm volatile("cp.async.commit_group;" ::: "memory")
#define CPA_WAIT0()  asm volatile("cp.async.wait_group 0;" ::: "memory")
__device__ __forceinline__ uint32_t smem_u32(const void* p) {
    uint32_t a;
    asm("{ .reg .u64 t; cvta.to.shared.u64 t, %1; cvt.u32.u64 %0, t; }" : "=r"(a) : "l"(p));
    return a;
}
__device__ __forceinline__ void ldsm4(uint32_t* r, uint32_t addr) {
    asm volatile("ldmatrix.sync.aligned.m8n8.x4.shared.b16 {%0,%1,%2,%3}, [%4];"
                 : "=r"(r[0]), "=r"(r[1]), "=r"(r[2]), "=r"(r[3]) : "r"(addr));
}
__device__ __forceinline__ void mma16(float* d, const uint32_t* a, uint32_t b0, uint32_t b1) {
    asm volatile(
        "mma.sync.aligned.m16n8k16.row.col.f32.f16.f16.f32 "
        "{%0,%1,%2,%3}, {%4,%5,%6,%7}, {%8,%9}, {%0,%1,%2,%3};"
        : "+f"(d[0]), "+f"(d[1]), "+f"(d[2]), "+f"(d[3])
        : "r"(a[0]), "r"(a[1]), "r"(a[2]), "r"(a[3]), "r"(b0), "r"(b1));
}

// ----------------- LN stats ------------------------------------------------
__global__ __launch_bounds__(256)
void ln_stats_kernel(const float* __restrict__ x) {
    int row = (blockIdx.x * 256 + threadIdx.x) >> 5;
    int lane = threadIdx.x & 31;
    const float4* xr = (const float4*)(x + (size_t)row * C_DIM);
    float s = 0.f, ss = 0.f;
#pragma unroll
    for (int i = 0; i < C_DIM / 128; ++i) {
        float4 v = xr[lane + 32 * i];
        s  += v.x + v.y + v.z + v.w;
        ss += v.x * v.x + v.y * v.y + v.z * v.z + v.w * v.w;
    }
#pragma unroll
    for (int o = 16; o; o >>= 1) {
        s  += __shfl_xor_sync(0xffffffffu, s, o);
        ss += __shfl_xor_sync(0xffffffffu, ss, o);
    }
    if (lane == 0) {
        float mu = s * (1.0f / C_DIM);
        float var = ss * (1.0f / C_DIM) - mu * mu;
        g_mu[row] = mu;
        g_rstd[row] = rsqrtf(var + 1e-5f);
    }
}

// ----------------- weight prep: transpose + fp16 round ----------------------
__global__ void prep_w_kernel(const float* __restrict__ WL,
                              const float* __restrict__ Wl1,
                              const float* __restrict__ Wl2) {
    int i = blockIdx.x * blockDim.x + threadIdx.x;
    if (i == 0) g_fix_count = 0;
    const int S1 = H_DIM * C_DIM;
    const int S2 = S1 + H_DIM * H_DIM;
    const int S3 = S2 + Q_DIM * H_DIM;
    if (i < S1) {
        int n = i / C_DIM, k = i % C_DIM;
        g_W1[i] = __float2half_rn(WL[(size_t)k * H_DIM + n]);
    } else if (i < S2) {
        int j = i - S1;
        int n = j / H_DIM, k = j % H_DIM;          // Wl1 top half: rows 0..511
        g_W2[j] = __float2half_rn(Wl1[(size_t)k * H_DIM + n]);
    } else if (i < S3) {
        int j = i - S2;
        int n = j / H_DIM, k = j % H_DIM;
        g_W3[j] = __float2half_rn(Wl2[(size_t)k * Q_DIM + n]);
    }
}

// ----------------- bias2 = noise_feature @ W_l1[512:,:] (exact fp32) -------
__global__ void bias2_kernel(const float* __restrict__ nf,
                             const float* __restrict__ Wl1) {
    int j = blockIdx.x * blockDim.x + threadIdx.x;
    const float* wp = Wl1 + (size_t)H_DIM * H_DIM + j;
    float s = 0.f;
    for (int k = 0; k < H_DIM; ++k)
        s += nf[k] * wp[(size_t)k * H_DIM];
    g_bias2[j] = s;
}

// ----------------- split-A fp16 mma.sync GEMM (B plain fp16) ---------------
// smem bytes: [0,1024): mu(128f)+rstd(128f)
//   A: base 1024, per buf 20480 (Ah 128 rows x 80B, Al same), 2 bufs -> 41984
//   B: base 41984, per buf 10240 (Bh 128 rows x 80B), 2 bufs -> 62464
#define AB0 1024
#define BB0 41984
#define GEMM_SMEM 62464

template <int MODE>
__global__ __launch_bounds__(256, 2)
void gemm_mma(const float* __restrict__ Aext,
              const float* __restrict__ lns, const float* __restrict__ lnb) {
    constexpr int K  = (MODE == 0) ? C_DIM : H_DIM;
    constexpr int Nn = (MODE == 2) ? Q_DIM : H_DIM;
    constexpr int KB = K / 32;

    extern __shared__ char sm[];
    float* smf = (float*)sm;
    const uint32_t sb = smem_u32(sm);
    const int tid = threadIdx.x;
    const int wid = tid >> 5, lane = tid & 31;
    const int g = lane >> 2, tg = lane & 3;
    const int wm = wid & 3, wn = wid >> 2;
    const int m0 = blockIdx.y * 128, n0 = blockIdx.x * 128;

    const __half* AhG = (MODE == 1) ? g_h1h : g_h2h;   // modes 1,2 only
    const __half* AlG = (MODE == 1) ? g_h1l : g_h2l;
    const __half* BG  = (MODE == 0) ? g_W1 : (MODE == 1 ? g_W2 : g_W3);

    if (MODE == 0 && tid < 128) {
        smf[tid]       = g_mu[m0 + tid];
        smf[128 + tid] = g_rstd[m0 + tid];
    }

    // MODE 0 A staging (fp32 + LN + split): thread -> (row, 16-wide k half)
    const int arow = tid >> 1;
    const int ak   = (tid & 1) * 16;
    const float* aP = (MODE == 0) ? Aext + (size_t)(m0 + arow) * K + ak : nullptr;
    // MODE 1/2 A staging (cp.async): thread -> row arow, 2 chunks of 16B
    const int aq = (tid & 1) * 2;
    const __half* ahP = (MODE != 0) ? AhG + (size_t)(m0 + arow) * K + aq * 8 : nullptr;
    const __half* alP = (MODE != 0) ? AlG + (size_t)(m0 + arow) * K + aq * 8 : nullptr;
    // B staging: thread -> rows brow, brow+64; 16B chunk bq of 4
    const int brow = tid >> 2;
    const int bq   = tid & 3;
    const __half* bP = BG + (size_t)(n0 + brow) * K + bq * 8;

    float4 aR[4];

    auto issueB = [&](int kb, int b) {
        uint32_t base = sb + BB0 + b * 10240 + brow * 80 + bq * 16;
        const __half* sh = bP + kb * 32;
        CPA16(base,           sh);
        CPA16(base + 64 * 80, sh + (size_t)64 * K);
    };
    auto issueA = [&](int kb, int b) {   // modes 1,2
        uint32_t base = sb + AB0 + b * 20480 + arow * 80 + aq * 16;
        const __half* sh = ahP + kb * 32;
        const __half* sl = alP + kb * 32;
        CPA16(base,              sh);
        CPA16(base + 16,         sh + 8);
        CPA16(base + 10240,      sl);
        CPA16(base + 10240 + 16, sl + 8);
    };
    auto loadA = [&](int kb) {           // mode 0
        const float* p = aP + kb * 32;
#pragma unroll
        for (int c = 0; c < 4; ++c) aR[c] = *(const float4*)(p + c * 4);
    };
    auto storeA = [&](int kb, int b) {   // mode 0
        char* dh = sm + AB0 + b * 20480 + arow * 80 + ak * 2;
        char* dl = dh + 10240;
        float mu = smf[arow], rs = smf[128 + arow];
        uint32_t hw[8], lw[8];
#pragma unroll
        for (int c = 0; c < 4; ++c) {
            float4 v = aR[c];
            int k = kb * 32 + ak + c * 4;
            float4 s4 = *(const float4*)(lns + k);
            float4 b4 = *(const float4*)(lnb + k);
            v.x = (v.x - mu) * rs * s4.x + b4.x;
            v.y = (v.y - mu) * rs * s4.y + b4.y;
            v.z = (v.z - mu) * rs * s4.z + b4.z;
            v.w = (v.w - mu) * rs * s4.w + b4.w;
            __half hx, lx, hy, ly, hz, lz, hwv, lwv;
            h16split(v.x, hx, lx); h16split(v.y, hy, ly);
            h16split(v.z, hz, lz); h16split(v.w, hwv, lwv);
            hw[c * 2]     = pack2(hx, hy);
            hw[c * 2 + 1] = pack2(hz, hwv);
            lw[c * 2]     = pack2(lx, ly);
            lw[c * 2 + 1] = pack2(lz, lwv);
        }
        *(uint4*)(dh)      = make_uint4(hw[0], hw[1], hw[2], hw[3]);
        *(uint4*)(dh + 16) = make_uint4(hw[4], hw[5], hw[6], hw[7]);
        *(uint4*)(dl)      = make_uint4(lw[0], lw[1], lw[2], lw[3]);
        *(uint4*)(dl + 16) = make_uint4(lw[4], lw[5], lw[6], lw[7]);
    };

    float acc[2][8][4];
#pragma unroll
    for (int mt = 0; mt < 2; ++mt)
#pragma unroll
        for (int nt = 0; nt < 8; ++nt)
#pragma unroll
            for (int j = 0; j < 4; ++j) acc[mt][nt][j] = 0.f;

    // ldmatrix lane-address components
    const int aRowL = lane & 15;
    const int aKhL  = lane >> 4;
    const int bRowL = (lane & 7) + ((lane >> 4) << 3);
    const int bKbL  = (lane >> 3) & 1;

    auto compute = [&](int b) {
        const uint32_t baseAh = sb + AB0 + b * 20480;
        const uint32_t baseAl = baseAh + 10240;
        const uint32_t baseB  = sb + BB0 + b * 10240;
#pragma unroll
        for (int ck = 0; ck < 2; ++ck) {
            const int k0 = ck * 16;
            const uint32_t aoff = (uint32_t)(aRowL * 80 + (k0 + aKhL * 8) * 2);
            const uint32_t boff = (uint32_t)(bRowL * 80 + (k0 + bKbL * 8) * 2);
            uint32_t ah[2][4], al[2][4];
#pragma unroll
            for (int mt = 0; mt < 2; ++mt) {
                uint32_t ro = (uint32_t)((wm * 32 + mt * 16) * 80);
                ldsm4(ah[mt], baseAh + ro + aoff);
                ldsm4(al[mt], baseAl + ro + aoff);
            }
#pragma unroll
            for (int p = 0; p < 4; ++p) {
                uint32_t co = (uint32_t)((wn * 64 + p * 16) * 80);
                uint32_t bh4[4];
                ldsm4(bh4, baseB + co + boff);
                const int n0t = p * 2, n1t = p * 2 + 1;
                // hi·B (4 independent accumulators)
                mma16(acc[0][n0t], ah[0], bh4[0], bh4[1]);
                mma16(acc[1][n0t], ah[1], bh4[0], bh4[1]);
                mma16(acc[0][n1t], ah[0], bh4[2], bh4[3]);
                mma16(acc[1][n1t], ah[1], bh4[2], bh4[3]);
                // lo·B
                mma16(acc[0][n0t], al[0], bh4[0], bh4[1]);
                mma16(acc[1][n0t], al[1], bh4[0], bh4[1]);
                mma16(acc[0][n1t], al[0], bh4[2], bh4[3]);
                mma16(acc[1][n1t], al[1], bh4[2], bh4[3]);
            }
        }
    };

    // ---- pipeline ----
    int buf = 0;
    if (MODE == 0) {
        issueB(0, 0);
        CPA_COMMIT();
        loadA(0);
        __syncthreads();          // mu/rstd visible
        storeA(0, 0);
        CPA_WAIT0();
        __syncthreads();
        for (int kt = 0; kt < KB; ++kt) {
            if (kt + 1 < KB) {
                issueB(kt + 1, buf ^ 1);
                CPA_COMMIT();
                loadA(kt + 1);
            }
            compute(buf);
            if (kt + 1 < KB) storeA(kt + 1, buf ^ 1);
            CPA_WAIT0();
            __syncthreads();
            buf ^= 1;
        }
    } else {
        issueB(0, 0);
        issueA(0, 0);
        CPA_COMMIT();
        CPA_WAIT0();
        __syncthreads();
        for (int kt = 0; kt < KB; ++kt) {
            if (kt + 1 < KB) {
                issueB(kt + 1, buf ^ 1);
                issueA(kt + 1, buf ^ 1);
                CPA_COMMIT();
            }
            compute(buf);
            CPA_WAIT0();
            __syncthreads();
            buf ^= 1;
        }
    }

    // ---- epilogue ----
#pragma unroll
    for (int mt = 0; mt < 2; ++mt) {
        int r = m0 + wm * 32 + mt * 16 + g;
#pragma unroll
        for (int nt = 0; nt < 8; ++nt) {
            int c = n0 + wn * 64 + nt * 8 + tg * 2;
            float* a4 = acc[mt][nt];
            if (MODE == 2) {
                float2 v0 = make_float2(gelu_f(a4[0]), gelu_f(a4[1]));
                float2 v1 = make_float2(gelu_f(a4[2]), gelu_f(a4[3]));
                *(float2*)(g_h3 + (size_t)r * Nn + c)       = v0;
                *(float2*)(g_h3 + (size_t)(r + 8) * Nn + c) = v1;
            } else {
                float b0 = 0.f, b1 = 0.f;
                if (MODE == 1) { b0 = g_bias2[c]; b1 = g_bias2[c + 1]; }
                float f0 = gelu_f(a4[0] + b0), f1 = gelu_f(a4[1] + b1);
                float f2 = gelu_f(a4[2] + b0), f3 = gelu_f(a4[3] + b1);
                __half h0, l0, h1, l1, h2, l2, h3, l3;
                h16split(f0, h0, l0); h16split(f1, h1, l1);
                h16split(f2, h2, l2); h16split(f3, h3, l3);
                __half* Dh = (MODE == 0) ? g_h1h : g_h2h;
                __half* Dl = (MODE == 0) ? g_h1l : g_h2l;
                *(uint32_t*)(Dh + (size_t)r * Nn + c)       = pack2(h0, h1);
                *(uint32_t*)(Dl + (size_t)r * Nn + c)       = pack2(l0, l1);
                *(uint32_t*)(Dh + (size_t)(r + 8) * Nn + c) = pack2(h2, h3);
                *(uint32_t*)(Dl + (size_t)(r + 8) * Nn + c) = pack2(l2, l3);
            }
        }
    }
}

// ----------------- final: logit, flag-or-write -----------------------------
__global__ __launch_bounds__(256)
void final_kernel(const float* __restrict__ x, const float* __restrict__ prevm,
                  const float* __restrict__ w3, float* __restrict__ out,
                  int write_extra) {
    int row = (blockIdx.x * 256 + threadIdx.x) >> 5;
    int lane = threadIdx.x & 31;
    const float* h3 = g_h3 + (size_t)row * Q_DIM;
    float s = 0.f;
#pragma unroll
    for (int i = 0; i < 8; ++i) s += h3[lane + 32 * i] * w3[lane + 32 * i];
#pragma unroll
    for (int o = 16; o; o >>= 1) s += __shfl_xor_sync(0xffffffffu, s, o);

    float prob = 1.0f / (1.0f + expf(-s));
    float xm = prob * prevm[row];

    if (fabsf(xm - 0.5f) < 4e-4f) {
        if (lane == 0) {
            int idx = atomicAdd(&g_fix_count, 1);
            if (idx < M_TOK) g_fix_list[idx] = row;
        }
        return;
    }
    float m = (xm > 0.5f) ? 1.0f : 0.0f;
    if (lane == 0 && write_extra) {
        out[(size_t)M_TOK * C_DIM + row] = m;
        out[(size_t)M_TOK * C_DIM + M_TOK + row] = (m > 0.f) ? 1.0f : 1e-10f;
    }
    const float4* xr = (const float4*)(x + (size_t)row * C_DIM);
    float4* orow = (float4*)(out + (size_t)row * C_DIM);
#pragma unroll
    for (int i = 0; i < 8; ++i) {
        float4 v = xr[lane + 32 * i];
        v.x *= m; v.y *= m; v.z *= m; v.w *= m;
        orow[lane + 32 * i] = v;
    }
}

// ----------------- batched fixup: exact fp32, 16 rows per block -------------
// dyn smem: sA[16][1024] fp32 (64KB) | sH[16][512] fp32 (32KB) | sMk[16]
#define FIX_ROWS 16
#define FIX_SMEM ((FIX_ROWS * 1024 + FIX_ROWS * 512 + 16) * 4)

__global__ __launch_bounds__(256)
void fixup_kernel(const float* __restrict__ x, const float* __restrict__ prevm,
                  const float* __restrict__ WL, const float* __restrict__ Wl1,
                  const float* __restrict__ Wl2, const float* __restrict__ w3,
                  const float* __restrict__ lns, const float* __restrict__ lnb,
                  float* __restrict__ out, int write_extra) {
    extern __shared__ float fs[];
    float* sA  = fs;                                   // [16][1024]
    float* sH  = fs + FIX_ROWS * 1024;                 // [16][512]
    float* sMk = fs + FIX_ROWS * 1024 + FIX_ROWS * 512;
    int cnt = g_fix_count;
    if (cnt > M_TOK) cnt = M_TOK;
    int t = threadIdx.x;

    for (int base = blockIdx.x * FIX_ROWS; base < cnt; base += gridDim.x * FIX_ROWS) {
        int nr = min(FIX_ROWS, cnt - base);
        // load + LN
        for (int r = 0; r < nr; ++r) {
            int row = g_fix_list[base + r];
            float mu = g_mu[row], rs = g_rstd[row];
            for (int j = t; j < C_DIM; j += 256)
                sA[r * C_DIM + j] = (x[(size_t)row * C_DIM + j] - mu) * rs * lns[j] + lnb[j];
        }
        __syncthreads();

        float a0[FIX_ROWS], a1[FIX_ROWS];
        // layer1: outputs j = t, t+256
#pragma unroll
        for (int r = 0; r < FIX_ROWS; ++r) { a0[r] = 0.f; a1[r] = 0.f; }
        for (int k = 0; k < C_DIM; ++k) {
            float w0 = WL[(size_t)k * H_DIM + t];
            float w1 = WL[(size_t)k * H_DIM + t + 256];
#pragma unroll
            for (int r = 0; r < FIX_ROWS; ++r) {
                float av = sA[r * C_DIM + k];
                a0[r] = fmaf(av, w0, a0[r]);
                a1[r] = fmaf(av, w1, a1[r]);
            }
        }
        __syncthreads();
        for (int r = 0; r < nr; ++r) {
            sH[r * H_DIM + t]       = gelu_f(a0[r]);
            sH[r * H_DIM + t + 256] = gelu_f(a1[r]);
        }
        __syncthreads();

        // layer2: outputs j = t, t+256 -> h2 into sA[r][0..512)
        {
            float b0 = g_bias2[t], b1 = g_bias2[t + 256];
#pragma unroll
            for (int r = 0; r < FIX_ROWS; ++r) { a0[r] = b0; a1[r] = b1; }
        }
        for (int k = 0; k < H_DIM; ++k) {
            float w0 = Wl1[(size_t)k * H_DIM + t];
            float w1 = Wl1[(size_t)k * H_DIM + t + 256];
#pragma unroll
            for (int r = 0; r < FIX_ROWS; ++r) {
                float hv = sH[r * H_DIM + k];
                a0[r] = fmaf(hv, w0, a0[r]);
                a1[r] = fmaf(hv, w1, a1[r]);
            }
        }
        __syncthreads();
        for (int r = 0; r < nr; ++r) {
            sA[r * C_DIM + t]       = gelu_f(a0[r]);
            sA[r * C_DIM + t + 256] = gelu_f(a1[r]);
        }
        __syncthreads();

        // layer3: output j = t (Q_DIM == 256 == blockDim)
#pragma unroll
        for (int r = 0; r < FIX_ROWS; ++r) a0[r] = 0.f;
        for (int k = 0; k < H_DIM; ++k) {
            float w0 = Wl2[(size_t)k * Q_DIM + t];
#pragma unroll
            for (int r = 0; r < FIX_ROWS; ++r)
                a0[r] = fmaf(sA[r * C_DIM + k], w0, a0[r]);
        }
        __syncthreads();
        for (int r = 0; r < nr; ++r)
            sH[r * H_DIM + t] = gelu_f(a0[r]);
        __syncthreads();

        // logit + mask: warp w handles rows w, w+8
        int w = t >> 5, l = t & 31;
        for (int rr = w; rr < nr; rr += 8) {
            float s = 0.f;
#pragma unroll
            for (int i = 0; i < 8; ++i)
                s += sH[rr * H_DIM + l + 32 * i] * w3[l + 32 * i];
#pragma unroll
            for (int o = 16; o; o >>= 1) s += __shfl_xor_sync(0xffffffffu, s, o);
            if (l == 0) {
                float prob = 1.0f / (1.0f + expf(-s));
                int row = g_fix_list[base + rr];
                float m = (prob * prevm[row] > 0.5f) ? 1.0f : 0.0f;
                sMk[rr] = m;
                if (write_extra) {
                    out[(size_t)M_TOK * C_DIM + row] = m;
                    out[(size_t)M_TOK * C_DIM + M_TOK + row] = (m > 0.f) ? 1.0f : 1e-10f;
                }
            }
        }
        __syncthreads();

        // gated output rows (256 float4 per row)
        for (int r = 0; r < nr; ++r) {
            int row = g_fix_list[base + r];
            float m = sMk[r];
            const float4* xr = (const float4*)(x + (size_t)row * C_DIM);
            float4* orow = (float4*)(out + (size_t)row * C_DIM);
            float4 v = xr[t];
            v.x *= m; v.y *= m; v.z *= m; v.w *= m;
            orow[t] = v;
        }
        __syncthreads();
    }
}

// ----------------- launch ---------------------------------------------------
extern "C" void kernel_launch(void* const* d_in, const int* in_sizes, int n_in,
                              void* d_out, int out_size) {
    const float* x   = (const float*)d_in[0];
    const float* nf  = (const float*)d_in[1];
    const float* pm  = (const float*)d_in[2];
    const float* lns = (const float*)d_in[3];
    const float* lnb = (const float*)d_in[4];
    const float* WL  = (const float*)d_in[5];
    const float* Wl1 = (const float*)d_in[6];
    const float* Wl2 = (const float*)d_in[7];
    const float* W3  = (const float*)d_in[8];
    float* out = (float*)d_out;

    cudaFuncSetAttribute(gemm_mma<0>, cudaFuncAttributeMaxDynamicSharedMemorySize, GEMM_SMEM);
    cudaFuncSetAttribute(gemm_mma<1>, cudaFuncAttributeMaxDynamicSharedMemorySize, GEMM_SMEM);
    cudaFuncSetAttribute(gemm_mma<2>, cudaFuncAttributeMaxDynamicSharedMemorySize, GEMM_SMEM);
    cudaFuncSetAttribute(fixup_kernel, cudaFuncAttributeMaxDynamicSharedMemorySize, FIX_SMEM);

    ln_stats_kernel<<<M_TOK / 8, 256>>>(x);
    prep_w_kernel<<<(H_DIM * C_DIM + H_DIM * H_DIM + Q_DIM * H_DIM + 255) / 256, 256>>>(WL, Wl1, Wl2);
    bias2_kernel<<<2, 256>>>(nf, Wl1);

    gemm_mma<0><<<dim3(H_DIM / 128, M_TOK / 128), 256, GEMM_SMEM>>>(x, lns, lnb);
    gemm_mma<1><<<dim3(H_DIM / 128, M_TOK / 128), 256, GEMM_SMEM>>>(nullptr, nullptr, nullptr);
    gemm_mma<2><<<dim3(Q_DIM / 128, M_TOK / 128), 256, GEMM_SMEM>>>(nullptr, nullptr, nullptr);

    int extra = (out_size >= M_TOK * C_DIM + 2 * M_TOK) ? 1 : 0;
    final_kernel<<<M_TOK / 8, 256>>>(x, pm, W3, out, extra);
    fixup_kernel<<<512, 256, FIX_SMEM>>>(x, pm, WL, Wl1, Wl2, W3, lns, lnb, out, extra);
}

// round 14
// speedup vs baseline: 6.5618x; 1.0479x over previous
#include <cuda_runtime.h>
#include <cuda_fp16.h>
#include <cstdint>

#define M_TOK 65536   // B*N
#define C_DIM 1024
#define H_DIM 512
#define Q_DIM 256

// ----------------- device-global scratch ----------------------------------
__device__ float g_mu[M_TOK];
__device__ float g_rstd[M_TOK];
__device__ float g_bias2[H_DIM];
// LN'd input, fp16 hi/lo pairs, [m][k]
__device__ __half g_a0h[(size_t)M_TOK * C_DIM];
__device__ __half g_a0l[(size_t)M_TOK * C_DIM];
// intermediates, fp16 hi/lo pairs, [m][k]
__device__ __half g_h1h[(size_t)M_TOK * H_DIM];
__device__ __half g_h1l[(size_t)M_TOK * H_DIM];
__device__ __half g_h2h[(size_t)M_TOK * H_DIM];
__device__ __half g_h2l[(size_t)M_TOK * H_DIM];
__device__ float  g_h3[(size_t)M_TOK * Q_DIM];
// fp16 weights (single rounding), TRANSPOSED [n][k]
__device__ __half g_W1[H_DIM * C_DIM];
__device__ __half g_W2[H_DIM * H_DIM];
__device__ __half g_W3[Q_DIM * H_DIM];
__device__ int   g_fix_count;
__device__ int   g_fix_list[M_TOK];

// ----------------- helpers ------------------------------------------------
__device__ __forceinline__ float gelu_f(float v) {
    return 0.5f * v * (1.0f + erff(v * 0.70710678118654752440f));
}
__device__ __forceinline__ void h16split(float x, __half& h, __half& l) {
    h = __float2half_rn(x);
    l = __float2half_rn(x - __half2float(h));
}
__device__ __forceinline__ uint32_t pack2(__half a, __half b) {
    __half2 h2 = __halves2half2(a, b);
    return *reinterpret_cast<uint32_t*>(&h2);
}
#define CPA16(dst, src) \
    asm volatile("cp.async.cg.shared.global [%0], [%1], 16;" :: "r"(dst), "l"(src) : "memory")
#define CPA_COMMIT() asm volatile("cp.async.commit_group;" ::: "memory")
#define CPA_WAIT0()  asm volatile("cp.async.wait_group 0;" ::: "memory")
#define CPA_WAIT1()  asm volatile("cp.async.wait_group 1;" ::: "memory")
__device__ __forceinline__ uint32_t smem_u32(const void* p) {
    uint32_t a;
    asm("{ .reg .u64 t; cvta.to.shared.u64 t, %1; cvt.u32.u64 %0, t; }" : "=r"(a) : "l"(p));
    return a;
}
__device__ __forceinline__ void ldsm4(uint32_t* r, uint32_t addr) {
    asm volatile("ldmatrix.sync.aligned.m8n8.x4.shared.b16 {%0,%1,%2,%3}, [%4];"
                 : "=r"(r[0]), "=r"(r[1]), "=r"(r[2]), "=r"(r[3]) : "r"(addr));
}
__device__ __forceinline__ void mma16(float* d, const uint32_t* a, uint32_t b0, uint32_t b1) {
    asm volatile(
        "mma.sync.aligned.m16n8k16.row.col.f32.f16.f16.f32 "
        "{%0,%1,%2,%3}, {%4,%5,%6,%7}, {%8,%9}, {%0,%1,%2,%3};"
        : "+f"(d[0]), "+f"(d[1]), "+f"(d[2]), "+f"(d[3])
        : "r"(a[0]), "r"(a[1]), "r"(a[2]), "r"(a[3]), "r"(b0), "r"(b1));
}

// ----------------- fused LN stats + apply + fp16 split ---------------------
__global__ __launch_bounds__(256)
void ln_apply_kernel(const float* __restrict__ x,
                     const float* __restrict__ lns, const float* __restrict__ lnb) {
    int row = (blockIdx.x * 256 + threadIdx.x) >> 5;
    int lane = threadIdx.x & 31;
    const float4* xr = (const float4*)(x + (size_t)row * C_DIM);
    float4 v[8];
    float s = 0.f, ss = 0.f;
#pragma unroll
    for (int i = 0; i < 8; ++i) {
        v[i] = xr[lane + 32 * i];
        s  += v[i].x + v[i].y + v[i].z + v[i].w;
        ss += v[i].x * v[i].x + v[i].y * v[i].y + v[i].z * v[i].z + v[i].w * v[i].w;
    }
#pragma unroll
    for (int o = 16; o; o >>= 1) {
        s  += __shfl_xor_sync(0xffffffffu, s, o);
        ss += __shfl_xor_sync(0xffffffffu, ss, o);
    }
    float mu = s * (1.0f / C_DIM);
    float var = ss * (1.0f / C_DIM) - mu * mu;
    float rs = rsqrtf(var + 1e-5f);
    if (lane == 0) { g_mu[row] = mu; g_rstd[row] = rs; }

    __half* dh = g_a0h + (size_t)row * C_DIM;
    __half* dl = g_a0l + (size_t)row * C_DIM;
#pragma unroll
    for (int i = 0; i < 8; ++i) {
        int k = (lane + 32 * i) * 4;
        float4 sc = *(const float4*)(lns + k);
        float4 bi = *(const float4*)(lnb + k);
        float f0 = (v[i].x - mu) * rs * sc.x + bi.x;
        float f1 = (v[i].y - mu) * rs * sc.y + bi.y;
        float f2 = (v[i].z - mu) * rs * sc.z + bi.z;
        float f3 = (v[i].w - mu) * rs * sc.w + bi.w;
        __half h0, l0, h1, l1, h2, l2, h3, l3;
        h16split(f0, h0, l0); h16split(f1, h1, l1);
        h16split(f2, h2, l2); h16split(f3, h3, l3);
        *(uint2*)(dh + k) = make_uint2(pack2(h0, h1), pack2(h2, h3));
        *(uint2*)(dl + k) = make_uint2(pack2(l0, l1), pack2(l2, l3));
    }
}

// ----------------- weight prep: transpose + fp16 round ----------------------
__global__ void prep_w_kernel(const float* __restrict__ WL,
                              const float* __restrict__ Wl1,
                              const float* __restrict__ Wl2) {
    int i = blockIdx.x * blockDim.x + threadIdx.x;
    if (i == 0) g_fix_count = 0;
    const int S1 = H_DIM * C_DIM;
    const int S2 = S1 + H_DIM * H_DIM;
    const int S3 = S2 + Q_DIM * H_DIM;
    if (i < S1) {
        int n = i / C_DIM, k = i % C_DIM;
        g_W1[i] = __float2half_rn(WL[(size_t)k * H_DIM + n]);
    } else if (i < S2) {
        int j = i - S1;
        int n = j / H_DIM, k = j % H_DIM;          // Wl1 top half: rows 0..511
        g_W2[j] = __float2half_rn(Wl1[(size_t)k * H_DIM + n]);
    } else if (i < S3) {
        int j = i - S2;
        int n = j / H_DIM, k = j % H_DIM;
        g_W3[j] = __float2half_rn(Wl2[(size_t)k * Q_DIM + n]);
    }
}

// ----------------- bias2 = noise_feature @ W_l1[512:,:] (exact fp32) -------
__global__ void bias2_kernel(const float* __restrict__ nf,
                             const float* __restrict__ Wl1) {
    int j = blockIdx.x * blockDim.x + threadIdx.x;
    const float* wp = Wl1 + (size_t)H_DIM * H_DIM + j;
    float s = 0.f;
    for (int k = 0; k < H_DIM; ++k)
        s += nf[k] * wp[(size_t)k * H_DIM];
    g_bias2[j] = s;
}

// ----------------- unified split-A fp16 GEMM, 3-stage cp.async --------------
// per stage: Ah 128x80B (10240) | Al 10240 | B 10240 = 30720; 3 stages
#define STAGE_BYTES 30720
#define GEMM_SMEM (3 * STAGE_BYTES)

template <int MODE>
__global__ __launch_bounds__(256, 2)
void gemm_mma() {
    constexpr int K  = (MODE == 0) ? C_DIM : H_DIM;
    constexpr int Nn = (MODE == 2) ? Q_DIM : H_DIM;
    constexpr int KB = K / 32;

    extern __shared__ char sm[];
    const uint32_t sb = smem_u32(sm);
    const int tid = threadIdx.x;
    const int wid = tid >> 5, lane = tid & 31;
    const int g = lane >> 2, tg = lane & 3;
    const int wm = wid & 3, wn = wid >> 2;
    const int m0 = blockIdx.y * 128, n0 = blockIdx.x * 128;

    const __half* AhG = (MODE == 0) ? g_a0h : (MODE == 1 ? g_h1h : g_h2h);
    const __half* AlG = (MODE == 0) ? g_a0l : (MODE == 1 ? g_h1l : g_h2l);
    const __half* BG  = (MODE == 0) ? g_W1  : (MODE == 1 ? g_W2  : g_W3);

    // A staging: thread -> row arow, 2 chunks of 16B (aq)
    const int arow = tid >> 1;
    const int aq   = (tid & 1) * 2;
    const __half* ahP = AhG + (size_t)(m0 + arow) * K + aq * 8;
    const __half* alP = AlG + (size_t)(m0 + arow) * K + aq * 8;
    // B staging: thread -> rows brow, brow+64; 16B chunk bq of 4
    const int brow = tid >> 2;
    const int bq   = tid & 3;
    const __half* bP = BG + (size_t)(n0 + brow) * K + bq * 8;

    auto issueAll = [&](int kb, int b) {
        uint32_t ab = sb + b * STAGE_BYTES + arow * 80 + aq * 16;
        const __half* sh = ahP + kb * 32;
        const __half* sl = alP + kb * 32;
        CPA16(ab,              sh);
        CPA16(ab + 16,         sh + 8);
        CPA16(ab + 10240,      sl);
        CPA16(ab + 10240 + 16, sl + 8);
        uint32_t bb = sb + b * STAGE_BYTES + 20480 + brow * 80 + bq * 16;
        const __half* bs = bP + kb * 32;
        CPA16(bb,           bs);
        CPA16(bb + 64 * 80, bs + (size_t)64 * K);
    };

    float acc[2][8][4];
#pragma unroll
    for (int mt = 0; mt < 2; ++mt)
#pragma unroll
        for (int nt = 0; nt < 8; ++nt)
#pragma unroll
            for (int j = 0; j < 4; ++j) acc[mt][nt][j] = 0.f;

    // ldmatrix lane-address components
    const int aRowL = lane & 15;
    const int aKhL  = lane >> 4;
    const int bRowL = (lane & 7) + ((lane >> 4) << 3);
    const int bKbL  = (lane >> 3) & 1;

    auto compute = [&](int b) {
        const uint32_t baseAh = sb + b * STAGE_BYTES;
        const uint32_t baseAl = baseAh + 10240;
        const uint32_t baseB  = baseAh + 20480;
#pragma unroll
        for (int ck = 0; ck < 2; ++ck) {
            const int k0 = ck * 16;
            const uint32_t aoff = (uint32_t)(aRowL * 80 + (k0 + aKhL * 8) * 2);
            const uint32_t boff = (uint32_t)(bRowL * 80 + (k0 + bKbL * 8) * 2);
            uint32_t ah[2][4], al[2][4];
#pragma unroll
            for (int mt = 0; mt < 2; ++mt) {
                uint32_t ro = (uint32_t)((wm * 32 + mt * 16) * 80);
                ldsm4(ah[mt], baseAh + ro + aoff);
                ldsm4(al[mt], baseAl + ro + aoff);
            }
#pragma unroll
            for (int p = 0; p < 4; ++p) {
                uint32_t co = (uint32_t)((wn * 64 + p * 16) * 80);
                uint32_t bh4[4];
                ldsm4(bh4, baseB + co + boff);
                const int n0t = p * 2, n1t = p * 2 + 1;
                mma16(acc[0][n0t], ah[0], bh4[0], bh4[1]);
                mma16(acc[1][n0t], ah[1], bh4[0], bh4[1]);
                mma16(acc[0][n1t], ah[0], bh4[2], bh4[3]);
                mma16(acc[1][n1t], ah[1], bh4[2], bh4[3]);
                mma16(acc[0][n0t], al[0], bh4[0], bh4[1]);
                mma16(acc[1][n0t], al[1], bh4[0], bh4[1]);
                mma16(acc[0][n1t], al[0], bh4[2], bh4[3]);
                mma16(acc[1][n1t], al[1], bh4[2], bh4[3]);
            }
        }
    };

    // ---- 3-stage pipeline ----
    issueAll(0, 0); CPA_COMMIT();
    issueAll(1, 1); CPA_COMMIT();
    CPA_WAIT1();                 // stage 0 landed
    __syncthreads();
    for (int kt = 0; kt < KB; ++kt) {
        compute(kt % 3);
        if (kt + 1 < KB) {
            if (kt + 2 < KB) {
                issueAll(kt + 2, (kt + 2) % 3);
                CPA_COMMIT();
                CPA_WAIT1();     // stage kt+1 landed
            } else {
                CPA_WAIT0();
            }
            __syncthreads();
        }
    }

    // ---- epilogue ----
#pragma unroll
    for (int mt = 0; mt < 2; ++mt) {
        int r = m0 + wm * 32 + mt * 16 + g;
#pragma unroll
        for (int nt = 0; nt < 8; ++nt) {
            int c = n0 + wn * 64 + nt * 8 + tg * 2;
            float* a4 = acc[mt][nt];
            if (MODE == 2) {
                float2 v0 = make_float2(gelu_f(a4[0]), gelu_f(a4[1]));
                float2 v1 = make_float2(gelu_f(a4[2]), gelu_f(a4[3]));
                *(float2*)(g_h3 + (size_t)r * Nn + c)       = v0;
                *(float2*)(g_h3 + (size_t)(r + 8) * Nn + c) = v1;
            } else {
                float b0 = 0.f, b1 = 0.f;
                if (MODE == 1) { b0 = g_bias2[c]; b1 = g_bias2[c + 1]; }
                float f0 = gelu_f(a4[0] + b0), f1 = gelu_f(a4[1] + b1);
                float f2 = gelu_f(a4[2] + b0), f3 = gelu_f(a4[3] + b1);
                __half h0, l0, h1, l1, h2, l2, h3, l3;
                h16split(f0, h0, l0); h16split(f1, h1, l1);
                h16split(f2, h2, l2); h16split(f3, h3, l3);
                __half* Dh = (MODE == 0) ? g_h1h : g_h2h;
                __half* Dl = (MODE == 0) ? g_h1l : g_h2l;
                *(uint32_t*)(Dh + (size_t)r * Nn + c)       = pack2(h0, h1);
                *(uint32_t*)(Dl + (size_t)r * Nn + c)       = pack2(l0, l1);
                *(uint32_t*)(Dh + (size_t)(r + 8) * Nn + c) = pack2(h2, h3);
                *(uint32_t*)(Dl + (size_t)(r + 8) * Nn + c) = pack2(l2, l3);
            }
        }
    }
}

// ----------------- final: logit, flag-or-write -----------------------------
__global__ __launch_bounds__(256)
void final_kernel(const float* __restrict__ x, const float* __restrict__ prevm,
                  const float* __restrict__ w3, float* __restrict__ out,
                  int write_extra) {
    int row = (blockIdx.x * 256 + threadIdx.x) >> 5;
    int lane = threadIdx.x & 31;
    const float* h3 = g_h3 + (size_t)row * Q_DIM;
    float s = 0.f;
#pragma unroll
    for (int i = 0; i < 8; ++i) s += h3[lane + 32 * i] * w3[lane + 32 * i];
#pragma unroll
    for (int o = 16; o; o >>= 1) s += __shfl_xor_sync(0xffffffffu, s, o);

    float prob = 1.0f / (1.0f + expf(-s));
    float xm = prob * prevm[row];

    if (fabsf(xm - 0.5f) < 4e-4f) {
        if (lane == 0) {
            int idx = atomicAdd(&g_fix_count, 1);
            if (idx < M_TOK) g_fix_list[idx] = row;
        }
        return;
    }
    float m = (xm > 0.5f) ? 1.0f : 0.0f;
    if (lane == 0 && write_extra) {
        out[(size_t)M_TOK * C_DIM + row] = m;
        out[(size_t)M_TOK * C_DIM + M_TOK + row] = (m > 0.f) ? 1.0f : 1e-10f;
    }
    const float4* xr = (const float4*)(x + (size_t)row * C_DIM);
    float4* orow = (float4*)(out + (size_t)row * C_DIM);
#pragma unroll
    for (int i = 0; i < 8; ++i) {
        float4 v = xr[lane + 32 * i];
        v.x *= m; v.y *= m; v.z *= m; v.w *= m;
        orow[lane + 32 * i] = v;
    }
}

// ----------------- batched fixup: exact fp32, 16 rows per block -------------
#define FIX_ROWS 16
#define FIX_SMEM ((FIX_ROWS * 1024 + FIX_ROWS * 512 + 16) * 4)

__global__ __launch_bounds__(256)
void fixup_kernel(const float* __restrict__ x, const float* __restrict__ prevm,
                  const float* __restrict__ WL, const float* __restrict__ Wl1,
                  const float* __restrict__ Wl2, const float* __restrict__ w3,
                  const float* __restrict__ lns, const float* __restrict__ lnb,
                  float* __restrict__ out, int write_extra) {
    extern __shared__ float fs[];
    float* sA  = fs;                                   // [16][1024]
    float* sH  = fs + FIX_ROWS * 1024;                 // [16][512]
    float* sMk = fs + FIX_ROWS * 1024 + FIX_ROWS * 512;
    int cnt = g_fix_count;
    if (cnt > M_TOK) cnt = M_TOK;
    int t = threadIdx.x;

    for (int base = blockIdx.x * FIX_ROWS; base < cnt; base += gridDim.x * FIX_ROWS) {
        int nr = min(FIX_ROWS, cnt - base);
        for (int r = 0; r < nr; ++r) {
            int row = g_fix_list[base + r];
            float mu = g_mu[row], rs = g_rstd[row];
            for (int j = t; j < C_DIM; j += 256)
                sA[r * C_DIM + j] = (x[(size_t)row * C_DIM + j] - mu) * rs * lns[j] + lnb[j];
        }
        __syncthreads();

        float a0[FIX_ROWS], a1[FIX_ROWS];
#pragma unroll
        for (int r = 0; r < FIX_ROWS; ++r) { a0[r] = 0.f; a1[r] = 0.f; }
        for (int k = 0; k < C_DIM; ++k) {
            float w0 = WL[(size_t)k * H_DIM + t];
            float w1 = WL[(size_t)k * H_DIM + t + 256];
#pragma unroll
            for (int r = 0; r < FIX_ROWS; ++r) {
                float av = sA[r * C_DIM + k];
                a0[r] = fmaf(av, w0, a0[r]);
                a1[r] = fmaf(av, w1, a1[r]);
            }
        }
        __syncthreads();
        for (int r = 0; r < nr; ++r) {
            sH[r * H_DIM + t]       = gelu_f(a0[r]);
            sH[r * H_DIM + t + 256] = gelu_f(a1[r]);
        }
        __syncthreads();

        {
            float b0 = g_bias2[t], b1 = g_bias2[t + 256];
#pragma unroll
            for (int r = 0; r < FIX_ROWS; ++r) { a0[r] = b0; a1[r] = b1; }
        }
        for (int k = 0; k < H_DIM; ++k) {
            float w0 = Wl1[(size_t)k * H_DIM + t];
            float w1 = Wl1[(size_t)k * H_DIM + t + 256];
#pragma unroll
            for (int r = 0; r < FIX_ROWS; ++r) {
                float hv = sH[r * H_DIM + k];
                a0[r] = fmaf(hv, w0, a0[r]);
                a1[r] = fmaf(hv, w1, a1[r]);
            }
        }
        __syncthreads();
        for (int r = 0; r < nr; ++r) {
            sA[r * C_DIM + t]       = gelu_f(a0[r]);
            sA[r * C_DIM + t + 256] = gelu_f(a1[r]);
        }
        __syncthreads();

#pragma unroll
        for (int r = 0; r < FIX_ROWS; ++r) a0[r] = 0.f;
        for (int k = 0; k < H_DIM; ++k) {
            float w0 = Wl2[(size_t)k * Q_DIM + t];
#pragma unroll
            for (int r = 0; r < FIX_ROWS; ++r)
                a0[r] = fmaf(sA[r * C_DIM + k], w0, a0[r]);
        }
        __syncthreads();
        for (int r = 0; r < nr; ++r)
            sH[r * H_DIM + t] = gelu_f(a0[r]);
        __syncthreads();

        int w = t >> 5, l = t & 31;
        for (int rr = w; rr < nr; rr += 8) {
            float s = 0.f;
#pragma unroll
            for (int i = 0; i < 8; ++i)
                s += sH[rr * H_DIM + l + 32 * i] * w3[l + 32 * i];
#pragma unroll
            for (int o = 16; o; o >>= 1) s += __shfl_xor_sync(0xffffffffu, s, o);
            if (l == 0) {
                float prob = 1.0f / (1.0f + expf(-s));
                int row = g_fix_list[base + rr];
                float m = (prob * prevm[row] > 0.5f) ? 1.0f : 0.0f;
                sMk[rr] = m;
                if (write_extra) {
                    out[(size_t)M_TOK * C_DIM + row] = m;
                    out[(size_t)M_TOK * C_DIM + M_TOK + row] = (m > 0.f) ? 1.0f : 1e-10f;
                }
            }
        }
        __syncthreads();

        for (int r = 0; r < nr; ++r) {
            int row = g_fix_list[base + r];
            float m = sMk[r];
            const float4* xr = (const float4*)(x + (size_t)row * C_DIM);
            float4* orow = (float4*)(out + (size_t)row * C_DIM);
            float4 v = xr[t];
            v.x *= m; v.y *= m; v.z *= m; v.w *= m;
            orow[t] = v;
        }
        __syncthreads();
    }
}

// ----------------- launch ---------------------------------------------------
extern "C" void kernel_launch(void* const* d_in, const int* in_sizes, int n_in,
                              void* d_out, int out_size) {
    const float* x   = (const float*)d_in[0];
    const float* nf  = (const float*)d_in[1];
    const float* pm  = (const float*)d_in[2];
    const float* lns = (const float*)d_in[3];
    const float* lnb = (const float*)d_in[4];
    const float* WL  = (const float*)d_in[5];
    const float* Wl1 = (const float*)d_in[6];
    const float* Wl2 = (const float*)d_in[7];
    const float* W3  = (const float*)d_in[8];
    float* out = (float*)d_out;

    cudaFuncSetAttribute(gemm_mma<0>, cudaFuncAttributeMaxDynamicSharedMemorySize, GEMM_SMEM);
    cudaFuncSetAttribute(gemm_mma<1>, cudaFuncAttributeMaxDynamicSharedMemorySize, GEMM_SMEM);
    cudaFuncSetAttribute(gemm_mma<2>, cudaFuncAttributeMaxDynamicSharedMemorySize, GEMM_SMEM);
    cudaFuncSetAttribute(fixup_kernel, cudaFuncAttributeMaxDynamicSharedMemorySize, FIX_SMEM);

    ln_apply_kernel<<<M_TOK / 8, 256>>>(x, lns, lnb);
    prep_w_kernel<<<(H_DIM * C_DIM + H_DIM * H_DIM + Q_DIM * H_DIM + 255) / 256, 256>>>(WL, Wl1, Wl2);
    bias2_kernel<<<2, 256>>>(nf, Wl1);

    gemm_mma<0><<<dim3(H_DIM / 128, M_TOK / 128), 256, GEMM_SMEM>>>();
    gemm_mma<1><<<dim3(H_DIM / 128, M_TOK / 128), 256, GEMM_SMEM>>>();
    gemm_mma<2><<<dim3(Q_DIM / 128, M_TOK / 128), 256, GEMM_SMEM>>>();

    int extra = (out_size >= M_TOK * C_DIM + 2 * M_TOK) ? 1 : 0;
    final_kernel<<<M_TOK / 8, 256>>>(x, pm, W3, out, extra);
    fixup_kernel<<<512, 256, FIX_SMEM>>>(x, pm, WL, Wl1, Wl2, W3, lns, lnb, out, extra);
}